// round 15
// baseline (speedup 1.0000x reference)
#include <cuda_runtime.h>
#include <cstdint>
#include <math.h>

#define B_  32
#define S_  2048
#define D_  512
#define M_TOTAL (B_ * S_)

// Device scratch (allocation-free): gate logits + fp16-packed weights.
__device__ float    g_logit[M_TOTAL];
__device__ uint32_t g_Wsh[D_ * D_ / 2];       // fp16 share weights
__device__ uint32_t g_Wlh[8 * D_ * D_ / 2];   // fp16 lang weights
__device__ uint32_t g_W1h[8 * D_ * D_ / 2];   // fp16 gate weights

// ---------------------------------------------------------------------------
// helpers
// ---------------------------------------------------------------------------
__device__ __forceinline__ uint32_t smem_u32(const void* p) {
    uint32_t a;
    asm("{ .reg .u64 t; cvta.to.shared.u64 t, %1; cvt.u32.u64 %0, t; }" : "=r"(a) : "l"(p));
    return a;
}
__device__ __forceinline__ uint32_t f16x2(float hi, float lo) {
    uint32_t r; asm("cvt.rn.f16x2.f32 %0, %1, %2;" : "=r"(r) : "f"(hi), "f"(lo)); return r;
}
__device__ __forceinline__ void mma_f16(float* c, const uint32_t* a, uint32_t b0, uint32_t b1) {
    asm volatile(
        "mma.sync.aligned.m16n8k16.row.col.f32.f16.f16.f32 "
        "{%0,%1,%2,%3}, {%4,%5,%6,%7}, {%8,%9}, {%0,%1,%2,%3};"
        : "+f"(c[0]), "+f"(c[1]), "+f"(c[2]), "+f"(c[3])
        : "r"(a[0]), "r"(a[1]), "r"(a[2]), "r"(a[3]), "r"(b0), "r"(b1));
}
__device__ __forceinline__ uint32_t lds32(uint32_t a) {
    uint32_t v; asm volatile("ld.shared.b32 %0, [%1];" : "=r"(v) : "r"(a)); return v;
}
__device__ __forceinline__ void sts128(uint32_t a, uint32_t x, uint32_t y, uint32_t z, uint32_t w) {
    asm volatile("st.shared.v4.b32 [%0], {%1,%2,%3,%4};"
                 :: "r"(a), "r"(x), "r"(y), "r"(z), "r"(w) : "memory");
}

#define CP16(d, s)  asm volatile("cp.async.cg.shared.global [%0], [%1], 16;" :: "r"(d), "l"(s))
#define CPCOMMIT()  asm volatile("cp.async.commit_group;" ::: "memory")
#define CPWAIT2()   asm volatile("cp.async.wait_group 2;" ::: "memory")

// ---------------------------------------------------------------------------
// Weight conversion: Ws/Wl/W1 -> packed fp16 (one pass).
// ---------------------------------------------------------------------------
__global__ void __launch_bounds__(256) kconv(
    const float* __restrict__ Ws, const float* __restrict__ Wl,
    const float* __restrict__ W1)
{
    int i = blockIdx.x * 256 + threadIdx.x;
    const int NWS = D_ * D_ / 4;
    const int NWL = 8 * D_ * D_ / 4;
    const float4* src; uint2* dst; int j;
    if (i < NWS)            { src = (const float4*)Ws; dst = (uint2*)g_Wsh; j = i; }
    else if (i < NWS + NWL) { src = (const float4*)Wl; dst = (uint2*)g_Wlh; j = i - NWS; }
    else                    { src = (const float4*)W1; dst = (uint2*)g_W1h; j = i - NWS - NWL; }
    float4 v = src[j];
    uint2 o; o.x = f16x2(v.y, v.x); o.y = f16x2(v.w, v.z);
    dst[j] = o;
}

// ---------------------------------------------------------------------------
// FP16 K=64 tile layout: row = 64 fp16 = 128B = 8 x 16B units; unit u of row r
// stored at byte r*128 + ((u ^ (r&7)) << 4).
// Fragment (m16n8k16) for k-step s, thread (g,t):
//   reg0/1 at o0 = ((2s)^g)<<4 + 4t (rows +0/+8 = +0/+1024B), reg2/3 at o0^16.
// mi (16-row step) = +2048 bytes.  [R13/R14 bug: was +4096 = 32 rows]
// ---------------------------------------------------------------------------

// ---------------------------------------------------------------------------
// Kernel 1: gate GEMM in FP16 (old_x @ W1^T) + fused relu/+old_x/.W2 epilogue.
// CTA tile 128x256, warp grid 4m x 4n, warp tile 32x64, occ 1.
// 8 chunks of K=64. A: LDG->cvt->STS (2 stages); B: cp.async (4 stages).
// ---------------------------------------------------------------------------
#define K1_A_STG  16384
#define K1_B_STG  32768
#define K1_SMEM   (K1_A_STG * 2 + K1_B_STG * 4)   // 160KB

__global__ void __launch_bounds__(512, 1) k1_gate(
    const float* __restrict__ old_x, const int* __restrict__ lang,
    const float* __restrict__ gb1,  const float* __restrict__ gW2)
{
    extern __shared__ __align__(128) char dsm[];
    const uint32_t sbA = smem_u32(dsm);
    const uint32_t sbB = sbA + K1_A_STG * 2;

    const int tid  = threadIdx.x;
    const int wid  = tid >> 5, lane = tid & 31;
    const int g    = lane >> 2, t = lane & 3;
    const int wm   = wid & 3,  wn  = wid >> 2;
    const int nt   = blockIdx.x;
    const int rt   = blockIdx.y;
    const int row0 = rt * 128;
    const int n0   = nt * 256;
    const int lg   = lang[rt >> 4];

    const float* gA = old_x + (size_t)row0 * D_;
    const float* b1l = gb1 + lg * D_;
    const float* W2l = gW2 + lg * D_;

    float cc[2][8][4];
    #pragma unroll
    for (int mi = 0; mi < 2; mi++)
        #pragma unroll
        for (int ni = 0; ni < 8; ni++)
            #pragma unroll
            for (int r = 0; r < 4; r++) cc[mi][ni][r] = 0.f;

    const int ar_ = tid >> 2, agi_ = tid & 3;
    const uint32_t aD0 = sbA + (uint32_t)(ar_ * 128 + (((2 * agi_)     ^ (ar_ & 7)) << 4));
    const uint32_t aD1 = sbA + (uint32_t)(ar_ * 128 + (((2 * agi_ + 1) ^ (ar_ & 7)) << 4));
    const float* aSrc = gA + (size_t)ar_ * D_ + agi_ * 16;
    float af[16];

    auto ldgA = [&](int c) {
        const float4* p = reinterpret_cast<const float4*>(aSrc + c * 64);
        #pragma unroll
        for (int q = 0; q < 4; q++) {
            float4 v = __ldg(p + q);
            af[q * 4 + 0] = v.x; af[q * 4 + 1] = v.y;
            af[q * 4 + 2] = v.z; af[q * 4 + 3] = v.w;
        }
    };
    auto stsA = [&](int c) {
        const uint32_t so = (uint32_t)((c & 1) * K1_A_STG);
        sts128(aD0 + so, f16x2(af[1], af[0]),  f16x2(af[3], af[2]),
                          f16x2(af[5], af[4]),  f16x2(af[7], af[6]));
        sts128(aD1 + so, f16x2(af[9], af[8]),  f16x2(af[11], af[10]),
                          f16x2(af[13], af[12]), f16x2(af[15], af[14]));
    };
    const size_t w1Base = ((size_t)lg * 512 + n0) << 8;   // u32 offset; 256 u32/row
    auto issueB = [&](int c) {
        const uint32_t stg = sbB + (uint32_t)((c & 3) * K1_B_STG);
        #pragma unroll
        for (int j = 0; j < 4; j++) {
            const int idx = j * 512 + tid;
            const int n = idx >> 3, gi = idx & 7;
            const uint32_t doff = (uint32_t)(n * 128 + ((gi ^ (n & 7)) << 4));
            CP16(stg + doff, g_W1h + w1Base + (size_t)n * 256 + c * 32 + gi * 4);
        }
    };

    ldgA(0); stsA(0);
    issueB(0); CPCOMMIT();
    issueB(1); CPCOMMIT();
    issueB(2); CPCOMMIT();
    ldgA(1);

    const uint32_t aBase = sbA + (uint32_t)((wm * 32 + g) * 128);
    const uint32_t bBase = sbB + (uint32_t)((wn * 64 + g) * 128);

    #pragma unroll 1
    for (int c = 0; c < 8; c++) {
        CPWAIT2();
        __syncthreads();
        const uint32_t stA = aBase + (uint32_t)((c & 1) * K1_A_STG);
        const uint32_t stB = bBase + (uint32_t)((c & 3) * K1_B_STG);
        #pragma unroll
        for (int s = 0; s < 4; s++) {
            const uint32_t o0 = ((uint32_t)((2 * s) ^ g) << 4) + t * 4;
            const uint32_t o1 = o0 ^ 16;
            uint32_t a[2][4];
            #pragma unroll
            for (int mi = 0; mi < 2; mi++) {
                const uint32_t ar = stA + (uint32_t)(mi * 2048);   // 16 rows x 128B
                a[mi][0] = lds32(ar + o0);
                a[mi][1] = lds32(ar + 1024 + o0);
                a[mi][2] = lds32(ar + o1);
                a[mi][3] = lds32(ar + 1024 + o1);
            }
            #pragma unroll
            for (int ni = 0; ni < 8; ni++) {
                const uint32_t br = stB + (uint32_t)(ni * 1024);
                const uint32_t b0 = lds32(br + o0);
                const uint32_t b1 = lds32(br + o1);
                mma_f16(cc[0][ni], a[0], b0, b1);
                mma_f16(cc[1][ni], a[1], b0, b1);
            }
        }
        if (c + 1 < 8) stsA(c + 1);
        if (c + 2 < 8) ldgA(c + 2);
        if (c + 3 < 8) issueB(c + 3);
        CPCOMMIT();                 // unconditional: keeps wait_group window sliding
    }

    #pragma unroll
    for (int mi = 0; mi < 2; mi++) {
        #pragma unroll
        for (int h = 0; h < 2; h++) {
            const int row = row0 + wm * 32 + mi * 16 + h * 8 + g;
            const float* oxr = old_x + (size_t)row * D_;
            float acc = 0.f;
            #pragma unroll
            for (int ni = 0; ni < 8; ni++) {
                const int e = n0 + wn * 64 + ni * 8 + 2 * t;
                float2 b1v = *reinterpret_cast<const float2*>(b1l + e);
                float2 w2v = *reinterpret_cast<const float2*>(W2l + e);
                float2 oxv = *reinterpret_cast<const float2*>(oxr + e);
                acc += (fmaxf(cc[mi][ni][2 * h]     + b1v.x, 0.f) + oxv.x) * w2v.x
                     + (fmaxf(cc[mi][ni][2 * h + 1] + b1v.y, 0.f) + oxv.y) * w2v.y;
            }
            acc += __shfl_xor_sync(0xFFFFFFFFu, acc, 1);
            acc += __shfl_xor_sync(0xFFFFFFFFu, acc, 2);
            if (t == 0) atomicAdd(&g_logit[row], acc);
        }
    }
}

// ---------------------------------------------------------------------------
// Kernel 2: fused dual GEMM in FP16.  out = (x@Ws^T)*(1-gv) + (x@Wl^T)*gv.
// CTA tile 128x128, warp tile 32x32 per GEMM, occ 1. 8 chunks of K=64.
// ---------------------------------------------------------------------------
#define K2_A_STG  16384
#define K2_B_STG  32768
#define K2_SMEM   (K2_A_STG * 2 + K2_B_STG * 4)   // 160KB

__global__ void __launch_bounds__(512, 1) k2_fused(
    const float* __restrict__ x, const int* __restrict__ lang,
    const float* __restrict__ gb2, float* __restrict__ out)
{
    extern __shared__ __align__(128) char dsm[];
    const uint32_t sbA = smem_u32(dsm);
    const uint32_t sbB = sbA + K2_A_STG * 2;

    const int tid  = threadIdx.x;
    const int wid  = tid >> 5, lane = tid & 31;
    const int g    = lane >> 2, t = lane & 3;
    const int wm   = wid & 3,  wn  = wid >> 2;
    const int nt   = blockIdx.x;
    const int rt   = blockIdx.y;
    const int row0 = rt * 128;
    const int n0   = nt * 128;
    const int lg   = lang[rt >> 4];

    const float* gA = x + (size_t)row0 * D_;
    const uint32_t* wsB = g_Wsh + (size_t)n0 * 256;
    const uint32_t* wlB = g_Wlh + ((size_t)lg * 512 + n0) * 256;
    const float bb2 = gb2[lg];

    float cs[2][4][4], cl[2][4][4];
    #pragma unroll
    for (int mi = 0; mi < 2; mi++)
        #pragma unroll
        for (int ni = 0; ni < 4; ni++)
            #pragma unroll
            for (int r = 0; r < 4; r++) { cs[mi][ni][r] = 0.f; cl[mi][ni][r] = 0.f; }

    const int ar_ = tid >> 2, agi_ = tid & 3;
    const uint32_t aD0 = sbA + (uint32_t)(ar_ * 128 + (((2 * agi_)     ^ (ar_ & 7)) << 4));
    const uint32_t aD1 = sbA + (uint32_t)(ar_ * 128 + (((2 * agi_ + 1) ^ (ar_ & 7)) << 4));
    const float* aSrc = gA + (size_t)ar_ * D_ + agi_ * 16;
    float af[16];

    auto ldgA = [&](int c) {
        const float4* p = reinterpret_cast<const float4*>(aSrc + c * 64);
        #pragma unroll
        for (int q = 0; q < 4; q++) {
            float4 v = __ldg(p + q);
            af[q * 4 + 0] = v.x; af[q * 4 + 1] = v.y;
            af[q * 4 + 2] = v.z; af[q * 4 + 3] = v.w;
        }
    };
    auto stsA = [&](int c) {
        const uint32_t so = (uint32_t)((c & 1) * K2_A_STG);
        sts128(aD0 + so, f16x2(af[1], af[0]),  f16x2(af[3], af[2]),
                          f16x2(af[5], af[4]),  f16x2(af[7], af[6]));
        sts128(aD1 + so, f16x2(af[9], af[8]),  f16x2(af[11], af[10]),
                          f16x2(af[13], af[12]), f16x2(af[15], af[14]));
    };
    auto issueB = [&](int c) {
        const uint32_t stg = sbB + (uint32_t)((c & 3) * K2_B_STG);
        #pragma unroll
        for (int j = 0; j < 2; j++) {
            const int idx = j * 512 + tid;
            const int n = idx >> 3, gi = idx & 7;
            const uint32_t doff = (uint32_t)(n * 128 + ((gi ^ (n & 7)) << 4));
            const size_t soff = (size_t)n * 256 + c * 32 + gi * 4;
            CP16(stg + doff,          wsB + soff);
            CP16(stg + 16384u + doff, wlB + soff);
        }
    };

    ldgA(0); stsA(0);
    issueB(0); CPCOMMIT();
    issueB(1); CPCOMMIT();
    issueB(2); CPCOMMIT();
    ldgA(1);

    const uint32_t aBase = sbA + (uint32_t)((wm * 32 + g) * 128);
    const uint32_t sBase = sbB + (uint32_t)((wn * 32 + g) * 128);

    #pragma unroll 1
    for (int c = 0; c < 8; c++) {
        CPWAIT2();
        __syncthreads();
        const uint32_t stA = aBase + (uint32_t)((c & 1) * K2_A_STG);
        const uint32_t stS = sBase + (uint32_t)((c & 3) * K2_B_STG);
        const uint32_t stL = stS + 16384u;
        #pragma unroll
        for (int s = 0; s < 4; s++) {
            const uint32_t o0 = ((uint32_t)((2 * s) ^ g) << 4) + t * 4;
            const uint32_t o1 = o0 ^ 16;
            uint32_t a[2][4];
            #pragma unroll
            for (int mi = 0; mi < 2; mi++) {
                const uint32_t ar = stA + (uint32_t)(mi * 2048);   // 16 rows x 128B
                a[mi][0] = lds32(ar + o0);
                a[mi][1] = lds32(ar + 1024 + o0);
                a[mi][2] = lds32(ar + o1);
                a[mi][3] = lds32(ar + 1024 + o1);
            }
            #pragma unroll
            for (int ni = 0; ni < 4; ni++) {
                const uint32_t srS = stS + (uint32_t)(ni * 1024);
                const uint32_t srL = stL + (uint32_t)(ni * 1024);
                const uint32_t s0 = lds32(srS + o0);
                const uint32_t s1 = lds32(srS + o1);
                const uint32_t l0 = lds32(srL + o0);
                const uint32_t l1 = lds32(srL + o1);
                mma_f16(cs[0][ni], a[0], s0, s1);
                mma_f16(cs[1][ni], a[1], s0, s1);
                mma_f16(cl[0][ni], a[0], l0, l1);
                mma_f16(cl[1][ni], a[1], l0, l1);
            }
        }
        if (c + 1 < 8) stsA(c + 1);
        if (c + 2 < 8) ldgA(c + 2);
        if (c + 3 < 8) issueB(c + 3);
        CPCOMMIT();                 // unconditional: keeps wait_group window sliding
    }

    #pragma unroll
    for (int mi = 0; mi < 2; mi++) {
        #pragma unroll
        for (int h = 0; h < 2; h++) {
            const int row = row0 + wm * 32 + mi * 16 + h * 8 + g;
            const float gv  = 1.f / (1.f + expf(-(g_logit[row] + bb2)));
            const float ngv = 1.f - gv;
            float* o = out + (size_t)row * D_ + n0 + wn * 32;
            #pragma unroll
            for (int ni = 0; ni < 4; ni++) {
                *reinterpret_cast<float2*>(o + ni * 8 + 2 * t) =
                    make_float2(cs[mi][ni][2 * h]     * ngv + cl[mi][ni][2 * h]     * gv,
                                cs[mi][ni][2 * h + 1] * ngv + cl[mi][ni][2 * h + 1] * gv);
            }
        }
    }
}

// ---------------------------------------------------------------------------
// launch
// ---------------------------------------------------------------------------
extern "C" void kernel_launch(void* const* d_in, const int* in_sizes, int n_in,
                              void* d_out, int out_size)
{
    const float* old_x  = (const float*)d_in[0];
    const float* x      = (const float*)d_in[1];
    const int*   lang   = (const int*)  d_in[2];
    const float* shareW = (const float*)d_in[3];
    const float* langsW = (const float*)d_in[4];
    const float* gW1    = (const float*)d_in[5];
    const float* gb1    = (const float*)d_in[6];
    const float* gW2    = (const float*)d_in[7];
    const float* gb2    = (const float*)d_in[8];
    float* out = (float*)d_out;

    cudaFuncSetAttribute(k1_gate,  cudaFuncAttributeMaxDynamicSharedMemorySize, K1_SMEM);
    cudaFuncSetAttribute(k2_fused, cudaFuncAttributeMaxDynamicSharedMemorySize, K2_SMEM);

    void* logit_ptr = nullptr;
    cudaGetSymbolAddress(&logit_ptr, g_logit);
    cudaMemsetAsync(logit_ptr, 0, M_TOTAL * sizeof(float));

    kconv<<<4352, 256>>>(shareW, langsW, gW1);

    k1_gate <<<dim3(2, M_TOTAL / 128), 512, K1_SMEM>>>(old_x, lang, gb1, gW2);
    k2_fused<<<dim3(D_ / 128, M_TOTAL / 128), 512, K2_SMEM>>>(x, lang, gb2, out);
}